// round 6
// baseline (speedup 1.0000x reference)
#include <cuda_runtime.h>
#include <math.h>

#define NEG_SLOPE 0.2f

// ---------------- scratch (device globals; no allocation allowed) ----------------
__device__ float g_d0n[3*320];
__device__ float g_d2n[3*320];
__device__ float g_dir1n[3*640];
__device__ float g_dir3n[3*640];
__device__ float g_dir4n[3*640];
__device__ float g_dir5n[3*640];
__device__ float g_wl1[64*3];
__device__ float g_wl2[64*3];
__device__ int   g_idx1[2*512*20];
__device__ int   g_idx2[2*4096*20];
__device__ float g_fm0[2*512*32];
__device__ float g_fm1[2*512*64];
__device__ float g_pc1[2*4096*3];
__device__ float g_fm2[2*4096*32];
__device__ float g_fm3[2*4096*64];
__device__ float g_fm4[2*4096*64];
__device__ float g_fm5[2*4096*64];
__device__ float g_fo [2*4096*704];

// ---------------- prep: normalize direction matrices, fold loop matmuls ----------
__global__ void prep_kernel(const float* __restrict__ d0, const float* __restrict__ d2,
                            const float* __restrict__ dir1, const float* __restrict__ dir3,
                            const float* __restrict__ dir4, const float* __restrict__ dir5,
                            const float* __restrict__ l1a, const float* __restrict__ l1b,
                            const float* __restrict__ l2a, const float* __restrict__ l2b)
{
    int t = blockIdx.x*blockDim.x + threadIdx.x;
    if (t < 3200) {
        const float* src; float* dst; int E; int e = t;
        if      (e < 320)  { src=d0;   dst=g_d0n;   E=320; }
        else if (e < 640)  { src=d2;   dst=g_d2n;   E=320; e-=320; }
        else if (e < 1280) { src=dir1; dst=g_dir1n; E=640; e-=640; }
        else if (e < 1920) { src=dir3; dst=g_dir3n; E=640; e-=1280; }
        else if (e < 2560) { src=dir4; dst=g_dir4n; E=640; e-=1920; }
        else               { src=dir5; dst=g_dir5n; E=640; e-=2560; }
        float x=src[e], y=src[E+e], z=src[2*E+e];
        float nrm = sqrtf(x*x+y*y+z*z);
        float inv = 1.f / fmaxf(nrm, 1e-12f);
        dst[e]=x*inv; dst[E+e]=y*inv; dst[2*E+e]=z*inv;
    } else if (t < 3200 + 384) {
        int o = t - 3200;
        const float* A; const float* B; float* W;
        if (o < 192) { A=l1a; B=l1b; W=g_wl1; } else { A=l2a; B=l2b; W=g_wl2; o-=192; }
        int f = o/3, c = o%3;
        float acc=0.f;
        for (int j=0;j<640;j++) acc += A[f*640+j]*B[j*3+c];
        W[f*3+c]=acc;
    }
}

// ---------------- knn: per-lane local top-20 + warp shfl merge -------------------
// Templated on N so the candidate scan fully unrolls (batched LDS, no runtime
// trip-count bookkeeping). One warp per query row; 8 warps/block amortize the
// shared coordinate fill; self-exclusion is predicated (SEL), not branched.
template<int N>
__global__ __launch_bounds__(256) void knn_kernel(const float* __restrict__ verts_ext,
                                                  int use_pc1, int idx_sel)
{
    __shared__ float shx[N], shy[N], shz[N];
    const float* V = use_pc1 ? (const float*)g_pc1 : verts_ext;
    int b = blockIdx.y;
    int* OUT = idx_sel ? g_idx2 : g_idx1;
    const float* Vb = V + (size_t)b*N*3;
    for (int i = threadIdx.x; i < N; i += 256) {
        shx[i]=Vb[i*3]; shy[i]=Vb[i*3+1]; shz[i]=Vb[i*3+2];
    }
    __syncthreads();
    int warp = threadIdx.x >> 5, lane = threadIdx.x & 31;
    int r = blockIdx.x*8 + warp;
    float qx=shx[r], qy=shy[r], qz=shz[r];

    float ld[20]; int li[20];
    #pragma unroll
    for (int t=0;t<20;t++){ld[t]=3.4e38f; li[t]=0;}
    float worst=3.4e38f; int wpos=0;
    #pragma unroll 4
    for (int it=0; it<N/32; it++) {
        int c = it*32 + lane;
        float dx=shx[c]-qx, dy=shy[c]-qy, dz=shz[c]-qz;
        float d = fmaf(dx,dx, fmaf(dy,dy, dz*dz));
        d = (c==r) ? 3.4e38f : d;          // predicated self-exclusion
        if (d < worst) {
            ld[wpos]=d; li[wpos]=c;
            worst=-1.f;
            #pragma unroll
            for (int t=0;t<20;t++) if (ld[t]>worst){worst=ld[t];wpos=t;}
        }
    }
    // local min for merge
    float lmin=3.4e38f; int lpos=0;
    #pragma unroll
    for (int t=0;t<20;t++) if (ld[t]<lmin){lmin=ld[t];lpos=t;}

    int* orow = OUT + ((size_t)b*N + r)*20;
    for (int sel=0; sel<20; sel++) {
        float v=lmin; int src=lane;
        #pragma unroll
        for (int off=16; off; off>>=1) {
            float v2=__shfl_xor_sync(0xffffffffu, v, off);
            int   s2=__shfl_xor_sync(0xffffffffu, src, off);
            if (v2<v || (v2==v && s2<src)) { v=v2; src=s2; }
        }
        int widx = __shfl_sync(0xffffffffu, li[lpos], src);
        if (lane==0) orow[sel]=widx;
        if (lane==src) {
            ld[lpos]=3.4e38f;
            lmin=3.4e38f; lpos=0;
            #pragma unroll
            for (int t=0;t<20;t++) if (ld[t]<lmin){lmin=ld[t];lpos=t;}
        }
    }
}

// ---------------- op3d: 1 warp per point (32 output channels) --------------------
__global__ __launch_bounds__(256) void op3d_kernel(const float* __restrict__ verts_ext,
                                                   int use_pc1, int N, int dir_sel, int idx_sel)
{
    const float* V = use_pc1 ? (const float*)g_pc1 : verts_ext;
    const float* SD = dir_sel ? g_d2n : g_d0n;           // [3][320]
    const int* IDX = idx_sel ? g_idx2 : g_idx1;
    float* OUT = idx_sel ? g_fm2 : g_fm0;
    int b = blockIdx.y;
    int warp = threadIdx.x>>5, lane = threadIdx.x&31;
    int n = blockIdx.x*8 + warp;
    if (n >= N) return;
    const float* Vb = V + (size_t)b*N*3;

    float sx[10], sy[10], sz[10];
    #pragma unroll
    for (int s=0;s<10;s++){
        int e = s*32 + lane;
        sx[s]=SD[e]; sy[s]=SD[320+e]; sz[s]=SD[640+e];
    }
    float nx=0.f, ny=0.f, nz=0.f;
    {
        float qx=Vb[n*3], qy=Vb[n*3+1], qz=Vb[n*3+2];
        if (lane<20) {
            int j = IDX[((size_t)b*N+n)*20 + lane];
            float dx=Vb[j*3]-qx, dy=Vb[j*3+1]-qy, dz=Vb[j*3+2]-qz;
            float nrm = sqrtf(fmaf(dx,dx,fmaf(dy,dy,dz*dz)));
            float inv = 1.f/fmaxf(nrm,1e-12f);
            nx=dx*inv; ny=dy*inv; nz=dz*inv;
        }
    }
    float best[10];
    #pragma unroll
    for (int s=0;s<10;s++) best[s]=0.f;   // theta = relu(.) >= 0
    #pragma unroll
    for (int k=0;k<20;k++) {
        float kx=__shfl_sync(0xffffffffu,nx,k);
        float ky=__shfl_sync(0xffffffffu,ny,k);
        float kz=__shfl_sync(0xffffffffu,nz,k);
        #pragma unroll
        for (int s=0;s<10;s++) {
            float t = fmaxf(fmaf(kx,sx[s],fmaf(ky,sy[s],kz*sz[s])), 0.f);
            best[s]=fmaxf(best[s],t);
        }
    }
    float acc=0.f;
    #pragma unroll
    for (int s=0;s<10;s++) acc+=best[s];
    OUT[((size_t)b*N+n)*32 + lane] = fmaxf(acc, 0.f);
}

// ---------------- fo = feat @ W + bias  (M x K) @ (K x 704) ----------------------
// Tile: 32 rows x 64 cols per block of 256 threads; thread computes 8 rows.
template<int K>
__global__ __launch_bounds__(256) void fo_gemm_kernel(const float* __restrict__ W,
                                                      const float* __restrict__ bias,
                                                      int feat_sel)
{
    const float* A = (feat_sel==0)?g_fm0:(feat_sel==1)?g_fm2:(feat_sel==2)?g_fm3:g_fm4;
    __shared__ float shAT[64*36];
    int tid = threadIdx.x;
    int rowBase = blockIdx.x*32;
    int cb = blockIdx.y*64 + (tid&63);
    int rg = tid>>6;
    #pragma unroll
    for (int idx=tid; idx<32*K; idx+=256) {
        int r = idx / K, k = idx - r*K;
        shAT[k*36+r] = A[(size_t)(rowBase+r)*K + k];
    }
    __syncthreads();
    float acc[8];
    #pragma unroll
    for (int j=0;j<8;j++) acc[j]=0.f;
    const float* Bp = W + cb;
    #pragma unroll 8
    for (int k=0;k<K;k++) {
        float bv = __ldg(&Bp[k*704]);
        const float4* a4 = (const float4*)&shAT[k*36 + rg*8];
        float4 a0=a4[0], a1=a4[1];
        acc[0]=fmaf(a0.x,bv,acc[0]); acc[1]=fmaf(a0.y,bv,acc[1]);
        acc[2]=fmaf(a0.z,bv,acc[2]); acc[3]=fmaf(a0.w,bv,acc[3]);
        acc[4]=fmaf(a1.x,bv,acc[4]); acc[5]=fmaf(a1.y,bv,acc[5]);
        acc[6]=fmaf(a1.z,bv,acc[6]); acc[7]=fmaf(a1.w,bv,acc[7]);
    }
    float bb = bias[cb];
    #pragma unroll
    for (int j=0;j<8;j++)
        g_fo[(size_t)(rowBase+rg*8+j)*704 + cb] = acc[j]+bb;
}

// ---------------- opnd main: 2 warps per point (64 output channels) --------------
__global__ __launch_bounds__(256) void opnd_kernel(const float* __restrict__ verts_ext,
                                                   int use_pc1, int N, int dir_sel, int idx_sel)
{
    const float* V = use_pc1 ? (const float*)g_pc1 : verts_ext;
    const float* SD = (dir_sel==0)?g_dir1n:(dir_sel==1)?g_dir3n:(dir_sel==2)?g_dir4n:g_dir5n;
    const int* IDX = idx_sel ? g_idx2 : g_idx1;
    float* OUT = (dir_sel==0)?g_fm1:(dir_sel==1)?g_fm3:(dir_sel==2)?g_fm4:g_fm5;
    int b = blockIdx.y;
    int warp = threadIdx.x>>5, lane = threadIdx.x&31;
    int n  = blockIdx.x*4 + (warp>>1);
    int oc = ((warp&1)<<5) + lane;
    if (n >= N) return;
    const float* Vb = V + (size_t)b*N*3;

    float sx[10], sy[10], sz[10];
    #pragma unroll
    for (int s=0;s<10;s++){
        int e=s*64+oc;
        sx[s]=SD[e]; sy[s]=SD[640+e]; sz[s]=SD[1280+e];
    }
    float nx=0.f,ny=0.f,nz=0.f; int myj=0;
    {
        float qx=Vb[n*3], qy=Vb[n*3+1], qz=Vb[n*3+2];
        if (lane<20) {
            myj = IDX[((size_t)b*N+n)*20+lane];
            float dx=Vb[myj*3]-qx, dy=Vb[myj*3+1]-qy, dz=Vb[myj*3+2]-qz;
            float nrm=sqrtf(fmaf(dx,dx,fmaf(dy,dy,dz*dz)));
            float inv=1.f/fmaxf(nrm,1e-12f);
            nx=dx*inv; ny=dy*inv; nz=dz*inv;
        }
    }
    const float* fo_b = g_fo + (size_t)b*N*704;

    float best[10];
    #pragma unroll
    for (int s=0;s<10;s++) best[s]=-3.4e38f;

    // process neighbors in pairs so two rows' loads are in flight simultaneously
    #pragma unroll
    for (int k=0;k<20;k+=2) {
        float kx0=__shfl_sync(0xffffffffu,nx,k),   ky0=__shfl_sync(0xffffffffu,ny,k),   kz0=__shfl_sync(0xffffffffu,nz,k);
        float kx1=__shfl_sync(0xffffffffu,nx,k+1), ky1=__shfl_sync(0xffffffffu,ny,k+1), kz1=__shfl_sync(0xffffffffu,nz,k+1);
        int j0 = __shfl_sync(0xffffffffu,myj,k);
        int j1 = __shfl_sync(0xffffffffu,myj,k+1);
        const float* fr0 = fo_b + (size_t)j0*704 + 64 + oc;
        const float* fr1 = fo_b + (size_t)j1*704 + 64 + oc;
        float f0[10], f1[10];
        #pragma unroll
        for (int s=0;s<10;s++) f0[s]=__ldg(&fr0[s*64]);
        #pragma unroll
        for (int s=0;s<10;s++) f1[s]=__ldg(&fr1[s*64]);
        #pragma unroll
        for (int s=0;s<10;s++) {
            float t0=fmaxf(fmaf(kx0,sx[s],fmaf(ky0,sy[s],kz0*sz[s])),0.f);
            float t1=fmaxf(fmaf(kx1,sx[s],fmaf(ky1,sy[s],kz1*sz[s])),0.f);
            best[s]=fmaxf(best[s], t0*f0[s]);
            best[s]=fmaxf(best[s], t1*f1[s]);
        }
    }
    float acc = fo_b[(size_t)n*704 + oc];
    #pragma unroll
    for (int s=0;s<10;s++) acc+=best[s];
    OUT[((size_t)b*N+n)*64+oc]=fmaxf(acc,0.f);
}

// ---------------- tree_gcn: one block per node, both batches fused ---------------
// Depth-4 rolling double buffer: 4 float4 weight loads in flight, 32 buffer regs.
// DRAM-bound on the 536MB branch2 stream.
__global__ __launch_bounds__(128) void gcn_kernel(const float* __restrict__ Wbr,
                                                  const float* __restrict__ rootW,
                                                  const float* __restrict__ biasp,
                                                  int act, int N, int x_sel, int wl_sel,
                                                  float* __restrict__ out, int write_pc1)
{
    __shared__ float sx0[64], sx1[64], sh0[512], sh1[512];
    const float* X  = x_sel ? g_fm5 : g_fm1;
    const float* WL = wl_sel ? g_wl2 : g_wl1;
    int n = blockIdx.x;
    int t = threadIdx.x;              // 128 threads
    if (t < 64) sx0[t]     = X[((size_t)n)*64 + t];
    else        sx1[t-64]  = X[((size_t)(N + n))*64 + (t-64)];

    const float4* Wp = (const float4*)(Wbr + (size_t)n*64*512) + t;
    float4 bufA[4], bufB[4];
    #pragma unroll
    for (int p=0;p<4;p++) bufA[p] = __ldg(&Wp[p*128]);
    __syncthreads();

    float a0[4]={0,0,0,0}, a1[4]={0,0,0,0};
    #pragma unroll
    for (int blk=0; blk<16; blk++) {
        // prefetch next 4 rows into the other buffer
        if (blk < 15) {
            if ((blk & 1) == 0) {
                #pragma unroll
                for (int p=0;p<4;p++) bufB[p] = __ldg(&Wp[((blk+1)*4+p)*128]);
            } else {
                #pragma unroll
                for (int p=0;p<4;p++) bufA[p] = __ldg(&Wp[((blk+1)*4+p)*128]);
            }
        }
        #pragma unroll
        for (int p=0;p<4;p++) {
            int i = blk*4 + p;
            float4 w = ((blk & 1) == 0) ? bufA[p] : bufB[p];
            float v0=sx0[i], v1=sx1[i];
            a0[0]=fmaf(v0,w.x,a0[0]); a0[1]=fmaf(v0,w.y,a0[1]);
            a0[2]=fmaf(v0,w.z,a0[2]); a0[3]=fmaf(v0,w.w,a0[3]);
            a1[0]=fmaf(v1,w.x,a1[0]); a1[1]=fmaf(v1,w.y,a1[1]);
            a1[2]=fmaf(v1,w.z,a1[2]); a1[3]=fmaf(v1,w.w,a1[3]);
        }
    }
    #pragma unroll
    for (int q=0;q<4;q++) {
        float h0=a0[q]; h0 = h0>0.f? h0 : NEG_SLOPE*h0;
        float h1=a1[q]; h1 = h1>0.f? h1 : NEG_SLOPE*h1;
        sh0[4*t+q]=h0; sh1[4*t+q]=h1;
    }
    __syncthreads();

    if (t < 48) {
        int bb=t/24; int r=t%24; int d=r/3, c=r%3;
        const float* hh = bb? sh1 : sh0;
        const float* xx = bb? sx1 : sx0;
        float root=0.f;
        #pragma unroll
        for (int i=0;i<64;i++) root = fmaf(xx[i], rootW[i*3+c], root);
        float br=0.f;
        const float* hd = hh + d*64;
        #pragma unroll
        for (int f=0;f<64;f++) br = fmaf(hd[f], WL[f*3+c], br);
        float o = root + br;
        if (act) { o += biasp[d*3+c]; o = o>0.f? o : NEG_SLOPE*o; }
        size_t m = (size_t)n*8 + d;
        size_t off = ((size_t)bb*N*8 + m)*3 + c;
        out[off] = o;
        if (write_pc1) g_pc1[off] = o;
    }
}

// ---------------- launch sequence -----------------------------------------------
extern "C" void kernel_launch(void* const* d_in, const int* in_sizes, int n_in,
                              void* d_out, int out_size)
{
    const float* pts    = (const float*)d_in[0];
    const float* d0     = (const float*)d_in[1];
    const float* w1     = (const float*)d_in[2];
    const float* b1     = (const float*)d_in[3];
    const float* dir1   = (const float*)d_in[4];
    const float* d2     = (const float*)d_in[5];
    const float* w3     = (const float*)d_in[6];
    const float* b3     = (const float*)d_in[7];
    const float* dir3   = (const float*)d_in[8];
    const float* w4     = (const float*)d_in[9];
    const float* b4     = (const float*)d_in[10];
    const float* dir4   = (const float*)d_in[11];
    const float* w5     = (const float*)d_in[12];
    const float* b5     = (const float*)d_in[13];
    const float* dir5   = (const float*)d_in[14];
    const float* root1  = (const float*)d_in[15];
    const float* branch1= (const float*)d_in[16];
    const float* l1a    = (const float*)d_in[17];
    const float* l1b    = (const float*)d_in[18];
    const float* bias1  = (const float*)d_in[19];
    const float* root2  = (const float*)d_in[20];
    const float* branch2= (const float*)d_in[21];
    const float* l2a    = (const float*)d_in[22];
    const float* l2b    = (const float*)d_in[23];
    float* out = (float*)d_out;

    prep_kernel<<<14,256>>>(d0,d2,dir1,dir3,dir4,dir5,l1a,l1b,l2a,l2b);

    // -------- stage A (512 points) --------
    knn_kernel<512> <<<dim3(64,2),256>>>(pts, 0, 0);
    op3d_kernel<<<dim3(64,2),256>>>(pts, 0, 512, 0, 0);
    fo_gemm_kernel<32><<<dim3(32,11),256>>>(w1, b1, 0);
    opnd_kernel<<<dim3(128,2),256>>>(pts, 0, 512, 0, 0);
    gcn_kernel<<<512,128>>>(branch1, root1, bias1, 1, 512, 0, 0, out, 1);

    // -------- stage B (4096 points) --------
    knn_kernel<4096> <<<dim3(512,2),256>>>(nullptr, 1, 1);
    op3d_kernel<<<dim3(512,2),256>>>(nullptr, 1, 4096, 1, 1);
    fo_gemm_kernel<32><<<dim3(256,11),256>>>(w3, b3, 1);
    opnd_kernel<<<dim3(1024,2),256>>>(nullptr, 1, 4096, 1, 1);
    fo_gemm_kernel<64><<<dim3(256,11),256>>>(w4, b4, 2);
    opnd_kernel<<<dim3(1024,2),256>>>(nullptr, 1, 4096, 2, 1);
    fo_gemm_kernel<64><<<dim3(256,11),256>>>(w5, b5, 3);
    opnd_kernel<<<dim3(1024,2),256>>>(nullptr, 1, 4096, 3, 1);
    gcn_kernel<<<4096,128>>>(branch2, root2, nullptr, 0, 4096, 1, 1, out + 2*4096*3, 0);
}